// round 6
// baseline (speedup 1.0000x reference)
#include <cuda_runtime.h>

#define N_NODES 50000
#define N_EDGES 200000
#define IN_C    32
#define HID     32
#define OUT_C   16
#define EDGE_DIM 8
#define LN_EPS  1e-5f

typedef unsigned long long u64;

// scatter accumulator; zero-initialized at module load, and node_kernel
// re-zeroes it after consuming, so the invariant holds across graph replays.
__device__ float g_agg[N_NODES * HID];

__device__ __forceinline__ u64 ffma2(u64 a, u64 b, u64 c) {
    u64 d;
    asm("fma.rn.f32x2 %0, %1, %2, %3;" : "=l"(d) : "l"(a), "l"(b), "l"(c));
    return d;
}
__device__ __forceinline__ u64 dup2(float s) {
    unsigned u = __float_as_uint(s);
    return ((u64)u << 32) | (u64)u;
}
__device__ __forceinline__ u64 pack2(float lo, float hi) {
    return ((u64)__float_as_uint(hi) << 32) | (u64)__float_as_uint(lo);
}
// packed relu: clear each 32-bit half whose sign bit is set (ALU pipe)
__device__ __forceinline__ u64 relu2(u64 v) {
    unsigned lo = (unsigned)v, hi = (unsigned)(v >> 32);
    lo &= ~(unsigned)((int)lo >> 31);
    hi &= ~(unsigned)((int)hi >> 31);
    return ((u64)hi << 32) | (u64)lo;
}
// vector reduction: one transaction adds 4 floats (16B-aligned)
__device__ __forceinline__ void red4(float* p, u64 a01, u64 a23) {
    asm volatile("red.global.add.v4.f32 [%0], {%1, %2, %3, %4};"
        :: "l"(p),
           "f"(__uint_as_float((unsigned)a01)),
           "f"(__uint_as_float((unsigned)(a01 >> 32))),
           "f"(__uint_as_float((unsigned)a23)),
           "f"(__uint_as_float((unsigned)(a23 >> 32)))
        : "memory");
}

// ---------------------------------------------------------------------------
// Edge kernel, f32x2-packed, quad-output lanes, v4 reduction scatter.
// Warp: q = lane & 7 owns output quad (4q..4q+3); es = lane >> 3 picks 2 of
// the warp's 8 edges. All 4 lane-subsets read identical w smem words
// (broadcast), amortizing w LDS over 8 edges.
// smem: sw4[(i*8+d)*8+q] = ulonglong2{ pack(w[4q],w[4q+1]), pack(w[4q+2],w[4q+3]) }
// ---------------------------------------------------------------------------
__global__ __launch_bounds__(128) void edge_kernel(
    const float* __restrict__ x,
    const int*   __restrict__ edge_index,
    const float* __restrict__ edge_attr,
    const float* __restrict__ nn_w,
    const float* __restrict__ nn_b)
{
    __shared__ ulonglong2 sw4[IN_C * EDGE_DIM * 8];  // 2048 * 16B = 32 KB
    __shared__ ulonglong2 sb4[IN_C * 8];             //  256 * 16B =  4 KB
    __shared__ u64        xs2[4][8][IN_C];           // warp x edge x feat = 8 KB

    const int tid = threadIdx.x;

    // stage nn_w: global [d][i*32 + 4q..4q+3] -> sw4[(i*8+d)*8+q]
    for (int idx = tid; idx < EDGE_DIM * IN_C * 8; idx += 128) {
        const int d = idx >> 8;
        const int j = idx & 255;
        const int i = j >> 3;
        const int q = j & 7;
        const float4 v = *(const float4*)(nn_w + d * (IN_C * HID) + i * HID + 4 * q);
        sw4[(i * EDGE_DIM + d) * 8 + q] = make_ulonglong2(pack2(v.x, v.y), pack2(v.z, v.w));
    }
    for (int idx = tid; idx < IN_C * 8; idx += 128) {
        const int i = idx >> 3;
        const int q = idx & 7;
        const float4 v = *(const float4*)(nn_b + i * HID + 4 * q);
        sb4[idx] = make_ulonglong2(pack2(v.x, v.y), pack2(v.z, v.w));
    }
    __syncthreads();

    const int lane = tid & 31;
    const int q    = lane & 7;
    const int es   = lane >> 3;          // 0..3, handles edges 2*es, 2*es+1
    const int warp = tid >> 5;
    const int gwarp = blockIdx.x * 4 + warp;
    const int warpsTotal = gridDim.x * 4;
    const int nGroups = N_EDGES / 8;     // 25000, exact

    for (int g = gwarp; g < nGroups; g += warpsTotal) {
        const int e0 = g * 8;

        // stage 8 source rows, pre-duplicated (coalesced per row)
        #pragma unroll
        for (int e = 0; e < 8; ++e) {
            const int s = edge_index[e0 + e];           // uniform -> bcast LDG
            xs2[warp][e][lane] = dup2(x[(size_t)s * IN_C + lane]);
        }
        __syncwarp();

        // my 2 edges: dst + packed-duplicated edge_attr
        const int eb = e0 + es * 2;
        int dst[2];
        u64 ea2[2][8];
        #pragma unroll
        for (int j = 0; j < 2; ++j) {
            dst[j] = edge_index[N_EDGES + eb + j];
            const float4 lo = *(const float4*)(edge_attr + (size_t)(eb + j) * EDGE_DIM);
            const float4 hi = *(const float4*)(edge_attr + (size_t)(eb + j) * EDGE_DIM + 4);
            ea2[j][0] = dup2(lo.x); ea2[j][1] = dup2(lo.y);
            ea2[j][2] = dup2(lo.z); ea2[j][3] = dup2(lo.w);
            ea2[j][4] = dup2(hi.x); ea2[j][5] = dup2(hi.y);
            ea2[j][6] = dup2(hi.z); ea2[j][7] = dup2(hi.w);
        }

        u64 m01[2] = {0ull, 0ull};
        u64 m23[2] = {0ull, 0ull};

        #pragma unroll 8
        for (int i = 0; i < IN_C; ++i) {
            ulonglong2 w[8];
            #pragma unroll
            for (int d = 0; d < 8; ++d) w[d] = sw4[(i * 8 + d) * 8 + q];  // LDS.128
            const ulonglong2 b = sb4[i * 8 + q];
            #pragma unroll
            for (int j = 0; j < 2; ++j) {
                const u64 xv = xs2[warp][es * 2 + j][i];   // bcast LDS.64
                u64 a01 = b.x, a23 = b.y;
                #pragma unroll
                for (int d = 0; d < 8; ++d) {
                    a01 = ffma2(ea2[j][d], w[d].x, a01);
                    a23 = ffma2(ea2[j][d], w[d].y, a23);
                }
                a01 = relu2(a01);
                a23 = relu2(a23);
                m01[j] = ffma2(xv, a01, m01[j]);
                m23[j] = ffma2(xv, a23, m23[j]);
            }
        }

        #pragma unroll
        for (int j = 0; j < 2; ++j)
            red4(&g_agg[(size_t)dst[j] * HID + 4 * q], m01[j], m23[j]);
        __syncwarp();  // xs2 reads done before next overwrite
    }
}

// ---------------------------------------------------------------------------
// Node kernel: h = agg + x@root + bias; LayerNorm; ReLU; out = h@lin_w+lin_b.
// Also re-zeroes g_agg after consuming it (replaces the zero kernel).
// ---------------------------------------------------------------------------
__global__ __launch_bounds__(256) void node_kernel(
    const float* __restrict__ x,
    const float* __restrict__ root,
    const float* __restrict__ bias,
    const float* __restrict__ norm_w,
    const float* __restrict__ norm_b,
    const float* __restrict__ lin_w,
    const float* __restrict__ lin_b,
    float* __restrict__ out)
{
    __shared__ float root_s[IN_C * HID];
    __shared__ float lw_s[HID * OUT_C];
    __shared__ float bias_s[HID], nw_s[HID], nb_s[HID], lb_s[OUT_C];

    const int tid = threadIdx.x;
    for (int i = tid; i < IN_C * HID; i += 256) root_s[i] = root[i];
    for (int i = tid; i < HID * OUT_C; i += 256) lw_s[i] = lin_w[i];
    if (tid < HID) { bias_s[tid] = bias[tid]; nw_s[tid] = norm_w[tid]; nb_s[tid] = norm_b[tid]; }
    if (tid < OUT_C) lb_s[tid] = lin_b[tid];
    __syncthreads();

    int n = blockIdx.x * blockDim.x + threadIdx.x;
    const int stride = gridDim.x * blockDim.x;
    const float4 z4 = make_float4(0.f, 0.f, 0.f, 0.f);
    for (; n < N_NODES; n += stride) {
        float h[HID];
        float4* aggp = (float4*)(g_agg + (size_t)n * HID);
        #pragma unroll
        for (int qq = 0; qq < HID / 4; ++qq) {
            float4 v = aggp[qq];
            h[qq * 4 + 0] = v.x + bias_s[qq * 4 + 0];
            h[qq * 4 + 1] = v.y + bias_s[qq * 4 + 1];
            h[qq * 4 + 2] = v.z + bias_s[qq * 4 + 2];
            h[qq * 4 + 3] = v.w + bias_s[qq * 4 + 3];
        }
        // reset accumulator for the next launch/replay
        #pragma unroll
        for (int qq = 0; qq < HID / 4; ++qq) aggp[qq] = z4;

        const float4* xp = (const float4*)(x + (size_t)n * IN_C);
        #pragma unroll
        for (int qq = 0; qq < IN_C / 4; ++qq) {
            float4 xv4 = xp[qq];
            float xv[4] = {xv4.x, xv4.y, xv4.z, xv4.w};
            #pragma unroll
            for (int s = 0; s < 4; ++s) {
                const int i = qq * 4 + s;
                #pragma unroll
                for (int o = 0; o < HID; ++o)
                    h[o] = fmaf(xv[s], root_s[i * HID + o], h[o]);
            }
        }

        float mu = 0.f;
        #pragma unroll
        for (int o = 0; o < HID; ++o) mu += h[o];
        mu *= (1.0f / HID);
        float var = 0.f;
        #pragma unroll
        for (int o = 0; o < HID; ++o) { float dd = h[o] - mu; var = fmaf(dd, dd, var); }
        var *= (1.0f / HID);
        const float inv = rsqrtf(var + LN_EPS);
        #pragma unroll
        for (int o = 0; o < HID; ++o)
            h[o] = fmaxf(fmaf((h[o] - mu) * inv, nw_s[o], nb_s[o]), 0.f);

        float res[OUT_C];
        #pragma unroll
        for (int oo = 0; oo < OUT_C; ++oo) res[oo] = lb_s[oo];
        #pragma unroll
        for (int k = 0; k < HID; ++k) {
            const float hv = h[k];
            #pragma unroll
            for (int oo = 0; oo < OUT_C; ++oo)
                res[oo] = fmaf(hv, lw_s[k * OUT_C + oo], res[oo]);
        }

        float4* op = (float4*)(out + (size_t)n * OUT_C);
        #pragma unroll
        for (int qq = 0; qq < OUT_C / 4; ++qq)
            op[qq] = make_float4(res[qq * 4 + 0], res[qq * 4 + 1], res[qq * 4 + 2], res[qq * 4 + 3]);
    }
}

extern "C" void kernel_launch(void* const* d_in, const int* in_sizes, int n_in,
                              void* d_out, int out_size) {
    const float* x          = (const float*)d_in[0];
    const int*   edge_index = (const int*)  d_in[1];
    const float* edge_attr  = (const float*)d_in[2];
    const float* nn_w       = (const float*)d_in[3];
    const float* nn_b       = (const float*)d_in[4];
    const float* root       = (const float*)d_in[5];
    const float* bias       = (const float*)d_in[6];
    const float* norm_w     = (const float*)d_in[7];
    const float* norm_b     = (const float*)d_in[8];
    const float* lin_w      = (const float*)d_in[9];
    const float* lin_b      = (const float*)d_in[10];
    float* out = (float*)d_out;

    edge_kernel<<<740, 128>>>(x, edge_index, edge_attr, nn_w, nn_b);
    node_kernel<<<(N_NODES + 255) / 256, 256>>>(x, root, bias, norm_w, norm_b,
                                                lin_w, lin_b, out);
}

// round 7
// speedup vs baseline: 2.2175x; 2.2175x over previous
#include <cuda_runtime.h>

#define N_NODES 50000
#define N_EDGES 200000
#define IN_C    32
#define HID     32
#define OUT_C   16
#define EDGE_DIM 8
#define LN_EPS  1e-5f

typedef unsigned long long u64;

__device__ float g_agg[N_NODES * HID];

__device__ __forceinline__ u64 ffma2(u64 a, u64 b, u64 c) {
    u64 d;
    asm("fma.rn.f32x2 %0, %1, %2, %3;" : "=l"(d) : "l"(a), "l"(b), "l"(c));
    return d;
}
__device__ __forceinline__ u64 dup2(float s) {
    unsigned u = __float_as_uint(s);
    return ((u64)u << 32) | (u64)u;
}
__device__ __forceinline__ u64 pack2(float lo, float hi) {
    return ((u64)__float_as_uint(hi) << 32) | (u64)__float_as_uint(lo);
}
// packed relu: clear each 32-bit half whose sign bit is set (ALU pipe)
__device__ __forceinline__ u64 relu2(u64 v) {
    unsigned lo = (unsigned)v, hi = (unsigned)(v >> 32);
    lo &= ~(unsigned)((int)lo >> 31);
    hi &= ~(unsigned)((int)hi >> 31);
    return ((u64)hi << 32) | (u64)lo;
}

__global__ __launch_bounds__(256) void zero_agg_kernel() {
    int i = blockIdx.x * blockDim.x + threadIdx.x;
    const int n4 = N_NODES * HID / 4;
    float4* p = (float4*)g_agg;
    const float4 z = make_float4(0.f, 0.f, 0.f, 0.f);
    for (; i < n4; i += gridDim.x * blockDim.x) p[i] = z;
}

// ---------------------------------------------------------------------------
// Edge kernel (R3 configuration — best measured).
// Warp: lane l -> p = l & 15 owns output pair (2p, 2p+1); eh = l >> 4 selects
// a 4-edge subset of the warp's 8-edge group. Both half-warps read identical
// w smem words (broadcast), amortizing w LDS over 8 edges.
// ---------------------------------------------------------------------------
__global__ __launch_bounds__(256) void edge_kernel(
    const float* __restrict__ x,
    const int*   __restrict__ edge_index,
    const float* __restrict__ edge_attr,
    const float* __restrict__ nn_w,
    const float* __restrict__ nn_b)
{
    __shared__ u64   sw2[IN_C * EDGE_DIM * 16];  // 4096 u64 = 32 KB
    __shared__ u64   sb2[IN_C * 16];             //  512 u64 =  4 KB
    __shared__ float xs_s[8][8][IN_C];           // warp x edge x feat = 8 KB

    const int tid = threadIdx.x;

    for (int idx = tid; idx < EDGE_DIM * 512; idx += 256) {
        const int d = idx >> 9;
        const int j = idx & 511;
        const int i = j >> 4;
        const int p = j & 15;
        const float2 v = *(const float2*)(nn_w + d * (IN_C * HID) + i * HID + 2 * p);
        sw2[(i * EDGE_DIM + d) * 16 + p] = pack2(v.x, v.y);
    }
    for (int idx = tid; idx < 512; idx += 256) {
        const int i = idx >> 4;
        const int p = idx & 15;
        const float2 v = *(const float2*)(nn_b + i * HID + 2 * p);
        sb2[i * 16 + p] = pack2(v.x, v.y);
    }
    __syncthreads();

    const int lane = tid & 31;
    const int p    = lane & 15;
    const int eh   = lane >> 4;
    const int warp = tid >> 5;
    const int gwarp = blockIdx.x * 8 + warp;
    const int warpsTotal = gridDim.x * 8;
    const int nGroups = N_EDGES / 8;  // 25000, exact

    for (int g = gwarp; g < nGroups; g += warpsTotal) {
        const int e0 = g * 8;

        #pragma unroll
        for (int e = 0; e < 8; ++e) {
            const int s = edge_index[e0 + e];
            xs_s[warp][e][lane] = x[(size_t)s * IN_C + lane];
        }

        const int eb = e0 + eh * 4;
        int dst[4];
        u64 ea2[4][8];
        #pragma unroll
        for (int e = 0; e < 4; ++e) {
            dst[e] = edge_index[N_EDGES + eb + e];
            const float4 lo = *(const float4*)(edge_attr + (size_t)(eb + e) * EDGE_DIM);
            const float4 hi = *(const float4*)(edge_attr + (size_t)(eb + e) * EDGE_DIM + 4);
            ea2[e][0] = dup2(lo.x); ea2[e][1] = dup2(lo.y);
            ea2[e][2] = dup2(lo.z); ea2[e][3] = dup2(lo.w);
            ea2[e][4] = dup2(hi.x); ea2[e][5] = dup2(hi.y);
            ea2[e][6] = dup2(hi.z); ea2[e][7] = dup2(hi.w);
        }
        __syncwarp();

        u64 msg2[4] = {0ull, 0ull, 0ull, 0ull};

        #pragma unroll 8
        for (int i = 0; i < IN_C; ++i) {
            u64 w[8];
            #pragma unroll
            for (int d = 0; d < 8; ++d) w[d] = sw2[(i * 8 + d) * 16 + p];
            const u64 b = sb2[i * 16 + p];
            #pragma unroll
            for (int e = 0; e < 4; ++e) {
                const u64 xv = dup2(xs_s[warp][eh * 4 + e][i]);  // smem bcast
                u64 a = b;
                #pragma unroll
                for (int d = 0; d < 8; ++d) a = ffma2(ea2[e][d], w[d], a);
                a = relu2(a);
                msg2[e] = ffma2(xv, a, msg2[e]);
            }
        }

        #pragma unroll
        for (int e = 0; e < 4; ++e) {
            float* base = &g_agg[(size_t)dst[e] * HID + 2 * p];
            atomicAdd(base,     __uint_as_float((unsigned)msg2[e]));
            atomicAdd(base + 1, __uint_as_float((unsigned)(msg2[e] >> 32)));
        }
        __syncwarp();
    }
}

// ---------------------------------------------------------------------------
// Node kernel, 4 lanes per node (spill-free, ~4x parallelism).
// Lane sub = t & 3 owns features [8*sub, 8*sub+8). Cross-lane reductions for
// LayerNorm and the final linear via shfl.xor within the quad (masks 1, 2).
// No early exit: node clamped, final store predicated (full shfl masks).
// ---------------------------------------------------------------------------
__global__ __launch_bounds__(256) void node_kernel(
    const float* __restrict__ x,
    const float* __restrict__ root,
    const float* __restrict__ bias,
    const float* __restrict__ norm_w,
    const float* __restrict__ norm_b,
    const float* __restrict__ lin_w,
    const float* __restrict__ lin_b,
    float* __restrict__ out)
{
    __shared__ float root_s[IN_C * HID];
    __shared__ float lw_s[HID * OUT_C];
    __shared__ float bias_s[HID], nw_s[HID], nb_s[HID], lb_s[OUT_C];

    const int tid = threadIdx.x;
    for (int i = tid; i < IN_C * HID; i += 256) root_s[i] = root[i];
    for (int i = tid; i < HID * OUT_C; i += 256) lw_s[i] = lin_w[i];
    if (tid < HID) { bias_s[tid] = bias[tid]; nw_s[tid] = norm_w[tid]; nb_s[tid] = norm_b[tid]; }
    if (tid < OUT_C) lb_s[tid] = lin_b[tid];
    __syncthreads();

    const int t = blockIdx.x * 256 + tid;
    const int rawNode = t >> 2;
    const bool valid = rawNode < N_NODES;
    const int node = valid ? rawNode : (N_NODES - 1);
    const int sub  = t & 3;
    const int fb   = sub * 8;            // this lane's feature base

    // load this lane's 8 agg features + 8 x features (32B each, coalesced)
    const float4* aggp = (const float4*)(g_agg + (size_t)node * HID + fb);
    const float4  a0 = aggp[0], a1 = aggp[1];
    const float4* xp = (const float4*)(x + (size_t)node * IN_C + fb);
    const float4  x0 = xp[0], x1 = xp[1];
    float xv8[8] = {x0.x, x0.y, x0.z, x0.w, x1.x, x1.y, x1.z, x1.w};

    float h[8];
    h[0] = a0.x + bias_s[fb + 0]; h[1] = a0.y + bias_s[fb + 1];
    h[2] = a0.z + bias_s[fb + 2]; h[3] = a0.w + bias_s[fb + 3];
    h[4] = a1.x + bias_s[fb + 4]; h[5] = a1.y + bias_s[fb + 5];
    h[6] = a1.z + bias_s[fb + 6]; h[7] = a1.w + bias_s[fb + 7];

    const int lane = tid & 31;
    const int quadBase = lane & ~3;

    // h += x @ root  (x[node][i] broadcast from owning quad lane)
    #pragma unroll
    for (int i = 0; i < IN_C; ++i) {
        const float xi = __shfl_sync(0xffffffffu, xv8[i & 7], quadBase + (i >> 3));
        #pragma unroll
        for (int j = 0; j < 8; ++j)
            h[j] = fmaf(xi, root_s[i * HID + fb + j], h[j]);
    }

    // LayerNorm across the quad
    float s = 0.f;
    #pragma unroll
    for (int j = 0; j < 8; ++j) s += h[j];
    s += __shfl_xor_sync(0xffffffffu, s, 1);
    s += __shfl_xor_sync(0xffffffffu, s, 2);
    const float mu = s * (1.0f / HID);

    float v = 0.f;
    #pragma unroll
    for (int j = 0; j < 8; ++j) { const float dd = h[j] - mu; v = fmaf(dd, dd, v); }
    v += __shfl_xor_sync(0xffffffffu, v, 1);
    v += __shfl_xor_sync(0xffffffffu, v, 2);
    const float inv = rsqrtf(v * (1.0f / HID) + LN_EPS);

    #pragma unroll
    for (int j = 0; j < 8; ++j)
        h[j] = fmaxf(fmaf((h[j] - mu) * inv, nw_s[fb + j], nb_s[fb + j]), 0.f);

    // partial final linear over this lane's 8 h-features
    float res[OUT_C];
    #pragma unroll
    for (int oo = 0; oo < OUT_C; ++oo) res[oo] = 0.f;
    #pragma unroll
    for (int k = 0; k < 8; ++k) {
        const float hv = h[k];
        #pragma unroll
        for (int oo = 0; oo < OUT_C; ++oo)
            res[oo] = fmaf(hv, lw_s[(fb + k) * OUT_C + oo], res[oo]);
    }
    // reduce across quad (all lanes end with full res)
    #pragma unroll
    for (int oo = 0; oo < OUT_C; ++oo) {
        res[oo] += __shfl_xor_sync(0xffffffffu, res[oo], 1);
        res[oo] += __shfl_xor_sync(0xffffffffu, res[oo], 2);
    }

    // lane sub writes outputs [4*sub, 4*sub+4) — static indices, predicated
    if (valid) {
        float* op = out + (size_t)node * OUT_C;
        #pragma unroll
        for (int oo = 0; oo < OUT_C; ++oo)
            if ((oo >> 2) == sub) op[oo] = res[oo] + lb_s[oo];
    }
}

extern "C" void kernel_launch(void* const* d_in, const int* in_sizes, int n_in,
                              void* d_out, int out_size) {
    const float* x          = (const float*)d_in[0];
    const int*   edge_index = (const int*)  d_in[1];
    const float* edge_attr  = (const float*)d_in[2];
    const float* nn_w       = (const float*)d_in[3];
    const float* nn_b       = (const float*)d_in[4];
    const float* root       = (const float*)d_in[5];
    const float* bias       = (const float*)d_in[6];
    const float* norm_w     = (const float*)d_in[7];
    const float* norm_b     = (const float*)d_in[8];
    const float* lin_w      = (const float*)d_in[9];
    const float* lin_b      = (const float*)d_in[10];
    float* out = (float*)d_out;

    zero_agg_kernel<<<296, 256>>>();
    edge_kernel<<<592, 256>>>(x, edge_index, edge_attr, nn_w, nn_b);
    node_kernel<<<(N_NODES * 4 + 255) / 256, 256>>>(x, root, bias, norm_w, norm_b,
                                                    lin_w, lin_b, out);
}

// round 9
// speedup vs baseline: 2.3009x; 1.0376x over previous
#include <cuda_runtime.h>

#define N_NODES 50000
#define N_EDGES 200000
#define IN_C    32
#define HID     32
#define OUT_C   16
#define EDGE_DIM 8
#define LN_EPS  1e-5f

typedef unsigned long long u64;

// scatter accumulator; zero-initialized at module load; node_kernel re-zeroes
// it after consuming, so the invariant holds across graph replays.
__device__ float g_agg[N_NODES * HID];

__device__ __forceinline__ u64 ffma2(u64 a, u64 b, u64 c) {
    u64 d;
    asm("fma.rn.f32x2 %0, %1, %2, %3;" : "=l"(d) : "l"(a), "l"(b), "l"(c));
    return d;
}
__device__ __forceinline__ u64 add2(u64 a, u64 b) {
    u64 d;
    asm("add.rn.f32x2 %0, %1, %2;" : "=l"(d) : "l"(a), "l"(b));
    return d;
}
__device__ __forceinline__ u64 dup2(float s) {
    unsigned u = __float_as_uint(s);
    return ((u64)u << 32) | (u64)u;
}
__device__ __forceinline__ u64 pack2(float lo, float hi) {
    return ((u64)__float_as_uint(hi) << 32) | (u64)__float_as_uint(lo);
}
__device__ __forceinline__ float lo2(u64 v) { return __uint_as_float((unsigned)v); }
__device__ __forceinline__ float hi2(u64 v) { return __uint_as_float((unsigned)(v >> 32)); }
// packed relu via FMNMX on the two halves (register pair aliasing: pack free)
__device__ __forceinline__ u64 relu2(u64 v) {
    return pack2(fmaxf(lo2(v), 0.f), fmaxf(hi2(v), 0.f));
}

// ---------------------------------------------------------------------------
// Edge kernel (R3 structure, FMNMX relu).
// Warp: lane l -> p = l & 15 owns output pair (2p, 2p+1); eh = l >> 4 selects
// a 4-edge subset of the warp's 8-edge group. Both half-warps read identical
// w smem words (broadcast), amortizing w LDS over 8 edges.
// ---------------------------------------------------------------------------
__global__ __launch_bounds__(256) void edge_kernel(
    const float* __restrict__ x,
    const int*   __restrict__ edge_index,
    const float* __restrict__ edge_attr,
    const float* __restrict__ nn_w,
    const float* __restrict__ nn_b)
{
    __shared__ u64   sw2[IN_C * EDGE_DIM * 16];  // 4096 u64 = 32 KB
    __shared__ u64   sb2[IN_C * 16];             //  512 u64 =  4 KB
    __shared__ float xs_s[8][8][IN_C];           // warp x edge x feat = 8 KB

    const int tid = threadIdx.x;

    for (int idx = tid; idx < EDGE_DIM * 512; idx += 256) {
        const int d = idx >> 9;
        const int j = idx & 511;
        const int i = j >> 4;
        const int p = j & 15;
        const float2 v = *(const float2*)(nn_w + d * (IN_C * HID) + i * HID + 2 * p);
        sw2[(i * EDGE_DIM + d) * 16 + p] = pack2(v.x, v.y);
    }
    for (int idx = tid; idx < 512; idx += 256) {
        const int i = idx >> 4;
        const int p = idx & 15;
        const float2 v = *(const float2*)(nn_b + i * HID + 2 * p);
        sb2[i * 16 + p] = pack2(v.x, v.y);
    }
    __syncthreads();

    const int lane = tid & 31;
    const int p    = lane & 15;
    const int eh   = lane >> 4;
    const int warp = tid >> 5;
    const int gwarp = blockIdx.x * 8 + warp;
    const int warpsTotal = gridDim.x * 8;
    const int nGroups = N_EDGES / 8;  // 25000, exact

    for (int g = gwarp; g < nGroups; g += warpsTotal) {
        const int e0 = g * 8;

        #pragma unroll
        for (int e = 0; e < 8; ++e) {
            const int s = edge_index[e0 + e];
            xs_s[warp][e][lane] = x[(size_t)s * IN_C + lane];
        }

        const int eb = e0 + eh * 4;
        int dst[4];
        u64 ea2[4][8];
        #pragma unroll
        for (int e = 0; e < 4; ++e) {
            dst[e] = edge_index[N_EDGES + eb + e];
            const float4 lo = *(const float4*)(edge_attr + (size_t)(eb + e) * EDGE_DIM);
            const float4 hi = *(const float4*)(edge_attr + (size_t)(eb + e) * EDGE_DIM + 4);
            ea2[e][0] = dup2(lo.x); ea2[e][1] = dup2(lo.y);
            ea2[e][2] = dup2(lo.z); ea2[e][3] = dup2(lo.w);
            ea2[e][4] = dup2(hi.x); ea2[e][5] = dup2(hi.y);
            ea2[e][6] = dup2(hi.z); ea2[e][7] = dup2(hi.w);
        }
        __syncwarp();

        u64 msg2[4] = {0ull, 0ull, 0ull, 0ull};

        #pragma unroll 8
        for (int i = 0; i < IN_C; ++i) {
            u64 w[8];
            #pragma unroll
            for (int d = 0; d < 8; ++d) w[d] = sw2[(i * 8 + d) * 16 + p];
            const u64 b = sb2[i * 16 + p];
            #pragma unroll
            for (int e = 0; e < 4; ++e) {
                const u64 xv = dup2(xs_s[warp][eh * 4 + e][i]);  // smem bcast
                u64 a = b;
                #pragma unroll
                for (int d = 0; d < 8; ++d) a = ffma2(ea2[e][d], w[d], a);
                a = relu2(a);
                msg2[e] = ffma2(xv, a, msg2[e]);
            }
        }

        #pragma unroll
        for (int e = 0; e < 4; ++e) {
            float* base = &g_agg[(size_t)dst[e] * HID + 2 * p];
            atomicAdd(base,     lo2(msg2[e]));
            atomicAdd(base + 1, hi2(msg2[e]));
        }
        __syncwarp();
    }
}

// ---------------------------------------------------------------------------
// Node kernel, 4 lanes per node, f32x2-packed compute. Lane sub = t & 3 owns
// features [8*sub, 8*sub+8) as 4 packed pairs. Quad shfl reductions for LN and
// the final linear. Also resets g_agg after consuming (replaces zero kernel).
// ---------------------------------------------------------------------------
__global__ __launch_bounds__(256) void node_kernel(
    const float* __restrict__ x,
    const float* __restrict__ root,
    const float* __restrict__ bias,
    const float* __restrict__ norm_w,
    const float* __restrict__ norm_b,
    const float* __restrict__ lin_w,
    const float* __restrict__ lin_b,
    float* __restrict__ out)
{
    __shared__ u64 root2[IN_C * 16];   // root packed: [i][pair]
    __shared__ u64 lw2[HID * 8];       // lin_w packed: [k][opair]
    __shared__ u64 bias2[16], nw2[16], nb2[16];
    __shared__ float lb_s[OUT_C];

    const int tid = threadIdx.x;
    for (int idx = tid; idx < IN_C * 16; idx += 256) {
        const int i = idx >> 4, pr = idx & 15;
        const float2 v = *(const float2*)(root + i * HID + 2 * pr);
        root2[idx] = pack2(v.x, v.y);
    }
    for (int idx = tid; idx < HID * 8; idx += 256) {
        const int k = idx >> 3, op = idx & 7;
        const float2 v = *(const float2*)(lin_w + k * OUT_C + 2 * op);
        lw2[idx] = pack2(v.x, v.y);
    }
    if (tid < 16) {
        const float2 b = *(const float2*)(bias + 2 * tid);
        const float2 w = *(const float2*)(norm_w + 2 * tid);
        const float2 nb = *(const float2*)(norm_b + 2 * tid);
        bias2[tid] = pack2(b.x, b.y);
        nw2[tid]   = pack2(w.x, w.y);
        nb2[tid]   = pack2(nb.x, nb.y);
    }
    if (tid < OUT_C) lb_s[tid] = lin_b[tid];
    __syncthreads();

    const int t = blockIdx.x * 256 + tid;
    const int rawNode = t >> 2;
    const bool valid = rawNode < N_NODES;
    const int node = valid ? rawNode : (N_NODES - 1);
    const int sub  = t & 3;
    const int fb   = sub * 8;            // feature base
    const int pb   = sub * 4;            // pair base

    const float4* aggp = (const float4*)(g_agg + (size_t)node * HID + fb);
    const float4  a0 = aggp[0], a1 = aggp[1];
    const float4* xp = (const float4*)(x + (size_t)node * IN_C + fb);
    const float4  x0 = xp[0], x1 = xp[1];
    float xv8[8] = {x0.x, x0.y, x0.z, x0.w, x1.x, x1.y, x1.z, x1.w};

    u64 h2[4];
    h2[0] = add2(pack2(a0.x, a0.y), bias2[pb + 0]);
    h2[1] = add2(pack2(a0.z, a0.w), bias2[pb + 1]);
    h2[2] = add2(pack2(a1.x, a1.y), bias2[pb + 2]);
    h2[3] = add2(pack2(a1.z, a1.w), bias2[pb + 3]);

    const int lane = tid & 31;
    const int quadBase = lane & ~3;

    // h += x @ root (packed: 4 ffma2 per input channel)
    #pragma unroll
    for (int i = 0; i < IN_C; ++i) {
        const u64 xi2 = dup2(__shfl_sync(0xffffffffu, xv8[i & 7], quadBase + (i >> 3)));
        #pragma unroll
        for (int j = 0; j < 4; ++j)
            h2[j] = ffma2(xi2, root2[i * 16 + pb + j], h2[j]);
    }

    // LayerNorm across the quad
    float s = 0.f;
    #pragma unroll
    for (int j = 0; j < 4; ++j) s += lo2(h2[j]) + hi2(h2[j]);
    s += __shfl_xor_sync(0xffffffffu, s, 1);
    s += __shfl_xor_sync(0xffffffffu, s, 2);
    const float mu = s * (1.0f / HID);
    const u64 negmu2 = dup2(-mu);

    u64 vacc = 0ull;
    u64 d2[4];
    #pragma unroll
    for (int j = 0; j < 4; ++j) {
        d2[j] = add2(h2[j], negmu2);
        vacc = ffma2(d2[j], d2[j], vacc);
    }
    float v = lo2(vacc) + hi2(vacc);
    v += __shfl_xor_sync(0xffffffffu, v, 1);
    v += __shfl_xor_sync(0xffffffffu, v, 2);
    const float inv = rsqrtf(v * (1.0f / HID) + LN_EPS);
    const u64 inv2 = dup2(inv);

    float h[8];
    #pragma unroll
    for (int j = 0; j < 4; ++j) {
        // ((h - mu) * inv) * nw + nb, then relu
        u64 t2 = ffma2(d2[j], inv2, 0ull);              // d * inv (+0)
        t2 = ffma2(t2, nw2[pb + j], nb2[pb + j]);
        h[2 * j + 0] = fmaxf(lo2(t2), 0.f);
        h[2 * j + 1] = fmaxf(hi2(t2), 0.f);
    }

    // partial final linear (packed output pairs: 8 u64 covering 16 outs)
    u64 res2[8];
    #pragma unroll
    for (int op = 0; op < 8; ++op) res2[op] = 0ull;
    #pragma unroll
    for (int k = 0; k < 8; ++k) {
        const u64 hv2 = dup2(h[k]);
        #pragma unroll
        for (int op = 0; op < 8; ++op)
            res2[op] = ffma2(hv2, lw2[(fb + k) * 8 + op], res2[op]);
    }
    // reduce across quad
    float res[OUT_C];
    #pragma unroll
    for (int op = 0; op < 8; ++op) {
        float rl = lo2(res2[op]), rh = hi2(res2[op]);
        rl += __shfl_xor_sync(0xffffffffu, rl, 1);
        rl += __shfl_xor_sync(0xffffffffu, rl, 2);
        rh += __shfl_xor_sync(0xffffffffu, rh, 1);
        rh += __shfl_xor_sync(0xffffffffu, rh, 2);
        res[2 * op + 0] = rl;
        res[2 * op + 1] = rh;
    }

    // reset accumulator for the next replay (after consumption)
    if (valid) {
        float4* ragg = (float4*)(g_agg + (size_t)node * HID + fb);
        const float4 z4 = make_float4(0.f, 0.f, 0.f, 0.f);
        ragg[0] = z4; ragg[1] = z4;
        // lane sub writes outputs [4*sub, 4*sub+4)
        float* op = out + (size_t)node * OUT_C;
        #pragma unroll
        for (int oo = 0; oo < OUT_C; ++oo)
            if ((oo >> 2) == sub) op[oo] = res[oo] + lb_s[oo];
    }
}

extern "C" void kernel_launch(void* const* d_in, const int* in_sizes, int n_in,
                              void* d_out, int out_size) {
    const float* x          = (const float*)d_in[0];
    const int*   edge_index = (const int*)  d_in[1];
    const float* edge_attr  = (const float*)d_in[2];
    const float* nn_w       = (const float*)d_in[3];
    const float* nn_b       = (const float*)d_in[4];
    const float* root       = (const float*)d_in[5];
    const float* bias       = (const float*)d_in[6];
    const float* norm_w     = (const float*)d_in[7];
    const float* norm_b     = (const float*)d_in[8];
    const float* lin_w      = (const float*)d_in[9];
    const float* lin_b      = (const float*)d_in[10];
    float* out = (float*)d_out;

    edge_kernel<<<592, 256>>>(x, edge_index, edge_attr, nn_w, nn_b);
    node_kernel<<<(N_NODES * 4 + 255) / 256, 256>>>(x, root, bias, norm_w, norm_b,
                                                    lin_w, lin_b, out);
}